// round 2
// baseline (speedup 1.0000x reference)
#include <cuda_runtime.h>
#include <math.h>

#define BB 256
#define VV 50257
#define UU 65536
#define MM 3
#define NE (MM * VV)   // 150771 entries

// ---------------- scratch -----------------------------------------------------
__device__ float g_probsT[(size_t)MM * VV * BB];   // [m][j][b], b contiguous (1KB rows), UNNORMALIZED exp
__device__ float g_sum[MM * BB];                   // row sums of exp
__device__ float g_scale[MM * BB];                 // w_m / sum
__device__ int   g_count[UU];
__device__ int   g_off[UU + 1];
__device__ int   g_cursor[UU];
__device__ int   g_entries[NE];                    // packed pidx = m*VV + j

// ---------------- CSR build ---------------------------------------------------
__global__ void zero_counts() {
    int i = blockIdx.x * blockDim.x + threadIdx.x;
    if (i < UU) g_count[i] = 0;
    if (i < MM * BB) g_sum[i] = 0.f;
}

__global__ void count_entries(const int* __restrict__ m0,
                              const int* __restrict__ m1,
                              const int* __restrict__ m2) {
    int idx = blockIdx.x * blockDim.x + threadIdx.x;
    if (idx >= NE) return;
    int m = idx / VV;
    int j = idx - m * VV;
    const int* mp = (m == 0) ? m0 : (m == 1) ? m1 : m2;
    atomicAdd(&g_count[mp[j]], 1);
}

// coalesced exclusive scan of 65536 counts: 1 block, 32 warps, warp-chunked
__global__ void scan_counts() {
    __shared__ int warp_tot[32];
    __shared__ int warp_pre[32];
    int t = threadIdx.x, lane = t & 31, w = t >> 5;
    const int CH = UU / 32;            // 2048 elements per warp
    int base = w * CH;

    // sweep 1: warp totals, fully coalesced
    int tot = 0;
    for (int i = lane; i < CH; i += 32) tot += g_count[base + i];
#pragma unroll
    for (int o = 16; o; o >>= 1) tot += __shfl_xor_sync(0xffffffffu, tot, o);
    if (lane == 0) warp_tot[w] = tot;
    __syncthreads();

    if (w == 0) {
        int v = warp_tot[lane];
        int s = v;
#pragma unroll
        for (int o = 1; o < 32; o <<= 1) {
            int x = __shfl_up_sync(0xffffffffu, s, o);
            if (lane >= o) s += x;
        }
        warp_pre[lane] = s - v;        // exclusive prefix of warp chunk
        if (lane == 31) g_off[UU] = s; // grand total
    }
    __syncthreads();

    // sweep 2: per-warp running exclusive scan, coalesced
    int run = warp_pre[w];
    for (int i = lane; i < CH; i += 32) {
        int v = g_count[base + i];     // L2-hot
        int s = v;
#pragma unroll
        for (int o = 1; o < 32; o <<= 1) {
            int x = __shfl_up_sync(0xffffffffu, s, o);
            if (lane >= o) s += x;
        }
        int excl = run + s - v;
        g_off[base + i]    = excl;
        g_cursor[base + i] = excl;
        run += __shfl_sync(0xffffffffu, s, 31);
    }
}

__global__ void fill_entries(const int* __restrict__ m0,
                             const int* __restrict__ m1,
                             const int* __restrict__ m2) {
    int idx = blockIdx.x * blockDim.x + threadIdx.x;
    if (idx >= NE) return;
    int m = idx / VV;
    int j = idx - m * VV;
    const int* mp = (m == 0) ? m0 : (m == 1) ? m1 : m2;
    int u = mp[j];
    int pos = atomicAdd(&g_cursor[u], 1);
    g_entries[pos] = idx;
}

// canonicalize order within each bucket (deterministic fp accumulation order)
__global__ void sort_buckets() {
    int u = blockIdx.x * blockDim.x + threadIdx.x;
    if (u >= UU) return;
    int s = g_off[u], e = g_off[u + 1];
    for (int i = s + 1; i < e; i++) {
        int key = g_entries[i];
        int k = i - 1;
        while (k >= s && g_entries[k] > key) { g_entries[k + 1] = g_entries[k]; k--; }
        g_entries[k + 1] = key;
    }
}

// ---------------- exp + transpose + row-sum (single pass over logits) ---------
// softmax is shift-invariant; logits are O(5) so exp() cannot overflow in fp32.
__global__ void exp_transpose_sum(const float* __restrict__ l0,
                                  const float* __restrict__ l1,
                                  const float* __restrict__ l2) {
    __shared__ float tile[32][33];
    int m  = blockIdx.z;
    int j0 = blockIdx.x * 32;
    int b0 = blockIdx.y * 32;
    const float* lg = (m == 0) ? l0 : (m == 1) ? l1 : l2;
    int tx = threadIdx.x, ty = threadIdx.y;     // (32, 8): warp == ty

    float vs[4];
#pragma unroll
    for (int k = 0; k < 4; k++) {
        int bl = ty + k * 8;
        int j  = j0 + tx;
        float v = 0.f;
        if (j < VV) v = __expf(lg[(size_t)(b0 + bl) * VV + j]);
        vs[k] = v;
        tile[bl][tx] = v;
    }
    // per-warp reduce over j (tx) for each of the warp's 4 batch rows
#pragma unroll
    for (int k = 0; k < 4; k++) {
        float s = vs[k];
#pragma unroll
        for (int o = 16; o; o >>= 1) s += __shfl_xor_sync(0xffffffffu, s, o);
        if (tx == 0) atomicAdd(&g_sum[m * BB + b0 + ty + k * 8], s);
    }
    __syncthreads();
#pragma unroll
    for (int k = 0; k < 4; k++) {
        int jl = ty + k * 8;
        int j  = j0 + jl;
        if (j < VV)
            g_probsT[((size_t)m * VV + j) * BB + b0 + tx] = tile[tx][jl];
    }
}

__global__ void finalize_scale(const float* __restrict__ w) {
    int t = threadIdx.x;
    if (t < MM * BB) g_scale[t] = w[t / BB] / g_sum[t];
}

// ---------------- gather: per-block flat entry list, MLP=8 pipeline -----------
#define CAP 512
__global__ void gather_union(float* __restrict__ out) {
    __shared__ float tile[32][257];            // [ul][b], padded: conflict-free
    __shared__ int soff[33];
    __shared__ int ep[CAP];
    __shared__ unsigned char eu[CAP];          // bits 0-4: ul, bits 6-7: model
    int u0 = blockIdx.x * 32;
    int t  = threadIdx.x;                      // t == batch index

    if (t < 33) soff[t] = g_off[u0 + t];
    float sc0 = g_scale[t], sc1 = g_scale[BB + t], sc2 = g_scale[2 * BB + t];
#pragma unroll
    for (int ul = 0; ul < 32; ul++) tile[ul][t] = 0.f;
    __syncthreads();

    int s0 = soff[0];
    int n  = soff[32] - s0;

    for (int c0 = 0; c0 < n; c0 += CAP) {
        int nc = min(n - c0, CAP);
        // stage entries + bucket/model tags (coalesced)
        for (int k = t; k < nc; k += 256) {
            int g    = s0 + c0 + k;
            int pidx = g_entries[g];
            ep[k] = pidx;
            int lo = 0, hi = 32;
            while (hi - lo > 1) { int mid = (lo + hi) >> 1; if (soff[mid] <= g) lo = mid; else hi = mid; }
            int mtag = (pidx >= VV) ? ((pidx >= 2 * VV) ? 128 : 64) : 0;
            eu[k] = (unsigned char)(lo | mtag);
        }
        __syncthreads();

        int k = 0;
        for (; k + 8 <= nc; k += 8) {
            float v0 = g_probsT[(size_t)ep[k + 0] * BB + t];
            float v1 = g_probsT[(size_t)ep[k + 1] * BB + t];
            float v2 = g_probsT[(size_t)ep[k + 2] * BB + t];
            float v3 = g_probsT[(size_t)ep[k + 3] * BB + t];
            float v4 = g_probsT[(size_t)ep[k + 4] * BB + t];
            float v5 = g_probsT[(size_t)ep[k + 5] * BB + t];
            float v6 = g_probsT[(size_t)ep[k + 6] * BB + t];
            float v7 = g_probsT[(size_t)ep[k + 7] * BB + t];
            int e;
            e = eu[k + 0]; tile[e & 31][t] += v0 * ((e & 64) ? sc1 : (e & 128) ? sc2 : sc0);
            e = eu[k + 1]; tile[e & 31][t] += v1 * ((e & 64) ? sc1 : (e & 128) ? sc2 : sc0);
            e = eu[k + 2]; tile[e & 31][t] += v2 * ((e & 64) ? sc1 : (e & 128) ? sc2 : sc0);
            e = eu[k + 3]; tile[e & 31][t] += v3 * ((e & 64) ? sc1 : (e & 128) ? sc2 : sc0);
            e = eu[k + 4]; tile[e & 31][t] += v4 * ((e & 64) ? sc1 : (e & 128) ? sc2 : sc0);
            e = eu[k + 5]; tile[e & 31][t] += v5 * ((e & 64) ? sc1 : (e & 128) ? sc2 : sc0);
            e = eu[k + 6]; tile[e & 31][t] += v6 * ((e & 64) ? sc1 : (e & 128) ? sc2 : sc0);
            e = eu[k + 7]; tile[e & 31][t] += v7 * ((e & 64) ? sc1 : (e & 128) ? sc2 : sc0);
        }
        for (; k < nc; k++) {
            float v = g_probsT[(size_t)ep[k] * BB + t];
            int e = eu[k];
            tile[e & 31][t] += v * ((e & 64) ? sc1 : (e & 128) ? sc2 : sc0);
        }
        __syncthreads();
    }

    // coalesced output: warp writes 32 consecutive u's for one b
    for (int it = 0; it < 32; it++) {
        int ul = t & 31;
        int b  = (t >> 5) + it * 8;
        out[(size_t)b * UU + u0 + ul] = tile[ul][b];
    }
}

// ---------------- launch -------------------------------------------------------
extern "C" void kernel_launch(void* const* d_in, const int* in_sizes, int n_in,
                              void* d_out, int out_size) {
    const float* l0 = (const float*)d_in[0];
    const float* l1 = (const float*)d_in[1];
    const float* l2 = (const float*)d_in[2];
    const int*   m0 = (const int*)d_in[3];
    const int*   m1 = (const int*)d_in[4];
    const int*   m2 = (const int*)d_in[5];
    const float* w  = (const float*)d_in[6];
    float* out = (float*)d_out;

    zero_counts<<<UU / 256, 256>>>();
    count_entries<<<(NE + 255) / 256, 256>>>(m0, m1, m2);
    scan_counts<<<1, 1024>>>();
    fill_entries<<<(NE + 255) / 256, 256>>>(m0, m1, m2);
    sort_buckets<<<UU / 256, 256>>>();

    exp_transpose_sum<<<dim3((VV + 31) / 32, BB / 32, MM), dim3(32, 8)>>>(l0, l1, l2);
    finalize_scale<<<1, MM * BB>>>(w);
    gather_union<<<UU / 32, 256>>>(out);
}

// round 3
// speedup vs baseline: 3.7361x; 3.7361x over previous
#include <cuda_runtime.h>
#include <math.h>

#define BB 256
#define VV 50257
#define UU 65536
#define MM 3
#define NE (MM * VV)   // 150771 total (model, vocab) entries

// ---------------- scratch (device globals; no allocation at launch time) ----
__device__ float g_probsT[(size_t)MM * VV * BB];   // [m][j][b], b contiguous (1KB rows)
__device__ float g_rmax[MM * BB];
__device__ float g_scale[MM * BB];                 // w_m / sum_exp
__device__ int   g_count[UU];
__device__ int   g_off[UU + 1];
__device__ int   g_cursor[UU];
__device__ int   g_entries[NE];                    // packed pidx = m*VV + j

// ---------------- CSR inverse-map build ------------------------------------
__global__ void zero_counts() {
    int i = blockIdx.x * blockDim.x + threadIdx.x;
    if (i < UU) g_count[i] = 0;
}

__global__ void count_entries(const int* __restrict__ m0,
                              const int* __restrict__ m1,
                              const int* __restrict__ m2) {
    int idx = blockIdx.x * blockDim.x + threadIdx.x;
    if (idx >= NE) return;
    int m = idx / VV;
    int j = idx - m * VV;
    const int* mp = (m == 0) ? m0 : (m == 1) ? m1 : m2;
    atomicAdd(&g_count[mp[j]], 1);
}

// coalesced exclusive scan of 65536 counts: 1 block, 32 warps, warp-chunked.
// (replaces the stride-64 per-thread version: every access here is a full
//  128B-coalesced warp transaction instead of 32 scattered sectors)
__global__ void scan_counts() {
    __shared__ int warp_tot[32];
    __shared__ int warp_pre[32];
    int t = threadIdx.x, lane = t & 31, w = t >> 5;
    const int CH = UU / 32;            // 2048 elements per warp
    int base = w * CH;

    // sweep 1: warp totals, fully coalesced
    int tot = 0;
    for (int i = lane; i < CH; i += 32) tot += g_count[base + i];
#pragma unroll
    for (int o = 16; o; o >>= 1) tot += __shfl_xor_sync(0xffffffffu, tot, o);
    if (lane == 0) warp_tot[w] = tot;
    __syncthreads();

    if (w == 0) {
        int v = warp_tot[lane];
        int s = v;
#pragma unroll
        for (int o = 1; o < 32; o <<= 1) {
            int x = __shfl_up_sync(0xffffffffu, s, o);
            if (lane >= o) s += x;
        }
        warp_pre[lane] = s - v;        // exclusive prefix of this warp's chunk
        if (lane == 31) g_off[UU] = s; // grand total
    }
    __syncthreads();

    // sweep 2: per-warp running exclusive scan, coalesced
    int run = warp_pre[w];
    for (int i = lane; i < CH; i += 32) {
        int v = g_count[base + i];     // L2-hot after sweep 1
        int s = v;
#pragma unroll
        for (int o = 1; o < 32; o <<= 1) {
            int x = __shfl_up_sync(0xffffffffu, s, o);
            if (lane >= o) s += x;
        }
        int excl = run + s - v;
        g_off[base + i]    = excl;
        g_cursor[base + i] = excl;
        run += __shfl_sync(0xffffffffu, s, 31);
    }
}

__global__ void fill_entries(const int* __restrict__ m0,
                             const int* __restrict__ m1,
                             const int* __restrict__ m2) {
    int idx = blockIdx.x * blockDim.x + threadIdx.x;
    if (idx >= NE) return;
    int m = idx / VV;
    int j = idx - m * VV;
    const int* mp = (m == 0) ? m0 : (m == 1) ? m1 : m2;
    int u = mp[j];
    int pos = atomicAdd(&g_cursor[u], 1);
    g_entries[pos] = idx;   // pidx = m*VV + j
}

// canonicalize entry order within each bucket (determinism across replays)
__global__ void sort_buckets() {
    int u = blockIdx.x * blockDim.x + threadIdx.x;
    if (u >= UU) return;
    int s = g_off[u], e = g_off[u + 1];
    for (int i = s + 1; i < e; i++) {
        int key = g_entries[i];
        int k = i - 1;
        while (k >= s && g_entries[k] > key) { g_entries[k + 1] = g_entries[k]; k--; }
        g_entries[k + 1] = key;
    }
}

// ---------------- softmax row stats (online max/sum) ------------------------
__global__ void rowstats(const float* __restrict__ l0,
                         const float* __restrict__ l1,
                         const float* __restrict__ l2,
                         const float* __restrict__ w) {
    int b = blockIdx.x, m = blockIdx.y, t = threadIdx.x;
    const float* row = ((m == 0) ? l0 : (m == 1) ? l1 : l2) + (size_t)b * VV;
    float mx = -1e30f, sm = 0.f;
    for (int j = t; j < VV; j += 256) {
        float x = row[j];
        if (x > mx) { sm = sm * __expf(mx - x) + 1.f; mx = x; }
        else        { sm += __expf(x - mx); }
    }
    __shared__ float smx[256], ssm[256];
    smx[t] = mx; ssm[t] = sm;
    __syncthreads();
    for (int s = 128; s > 0; s >>= 1) {
        if (t < s) {
            float amx = smx[t], as = ssm[t], bmx = smx[t + s], bs = ssm[t + s];
            float Mx = fmaxf(amx, bmx);
            ssm[t] = as * __expf(amx - Mx) + bs * __expf(bmx - Mx);
            smx[t] = Mx;
        }
        __syncthreads();
    }
    if (t == 0) {
        g_rmax[m * BB + b]  = smx[0];
        g_scale[m * BB + b] = w[m] / ssm[0];
    }
}

// ---------------- exp + transpose: logits[b][j] -> probsT[m][j][b] ----------
__global__ void exp_transpose(const float* __restrict__ l0,
                              const float* __restrict__ l1,
                              const float* __restrict__ l2) {
    __shared__ float tile[32][33];
    int m  = blockIdx.z;
    int j0 = blockIdx.x * 32;
    int b0 = blockIdx.y * 32;
    const float* lg = (m == 0) ? l0 : (m == 1) ? l1 : l2;
    int tx = threadIdx.x, ty = threadIdx.y;   // (32, 8)

#pragma unroll
    for (int k = 0; k < 4; k++) {
        int bl = ty + k * 8;
        int j  = j0 + tx;
        int b  = b0 + bl;
        float v = 0.f;
        if (j < VV) {
            float x  = lg[(size_t)b * VV + j];
            int rid  = m * BB + b;
            v = __expf(x - g_rmax[rid]) * g_scale[rid];
        }
        tile[bl][tx] = v;
    }
    __syncthreads();
#pragma unroll
    for (int k = 0; k < 4; k++) {
        int jl = ty + k * 8;
        int j  = j0 + jl;
        if (j < VV)
            g_probsT[((size_t)m * VV + j) * BB + b0 + tx] = tile[tx][jl];
    }
}

// ---------------- gather per union column, smem-transpose, coalesced write --
__global__ void gather_union(float* __restrict__ out) {
    __shared__ float tile[32][257];   // 32 u x 256 b, padded: conflict-free both ways
    int u0 = blockIdx.x * 32;
    int t  = threadIdx.x;             // 256 threads: thread t = batch index in phase 1

    for (int ul = 0; ul < 32; ul++) {
        int u = u0 + ul;
        int s = g_off[u], e = g_off[u + 1];
        float acc = 0.f;
        for (int ee = s; ee < e; ee++) {
            int p = g_entries[ee];
            acc += g_probsT[(size_t)p * BB + t];   // contiguous 1KB per entry
        }
        tile[ul][t] = acc;
    }
    __syncthreads();
    // write out[b][u0..u0+31]: 32-thread groups -> one 128B transaction each
    for (int it = 0; it < 32; it++) {
        int ul = t & 31;
        int b  = (t >> 5) + it * 8;
        out[(size_t)b * UU + u0 + ul] = tile[ul][b];
    }
}

// ---------------- launch -----------------------------------------------------
extern "C" void kernel_launch(void* const* d_in, const int* in_sizes, int n_in,
                              void* d_out, int out_size) {
    const float* l0 = (const float*)d_in[0];
    const float* l1 = (const float*)d_in[1];
    const float* l2 = (const float*)d_in[2];
    const int*   m0 = (const int*)d_in[3];
    const int*   m1 = (const int*)d_in[4];
    const int*   m2 = (const int*)d_in[5];
    const float* w  = (const float*)d_in[6];
    float* out = (float*)d_out;

    zero_counts<<<UU / 256, 256>>>();
    count_entries<<<(NE + 255) / 256, 256>>>(m0, m1, m2);
    scan_counts<<<1, 1024>>>();
    fill_entries<<<(NE + 255) / 256, 256>>>(m0, m1, m2);
    sort_buckets<<<UU / 256, 256>>>();

    rowstats<<<dim3(BB, MM), 256>>>(l0, l1, l2, w);
    exp_transpose<<<dim3((VV + 31) / 32, BB / 32, MM), dim3(32, 8)>>>(l0, l1, l2);
    gather_union<<<UU / 32, 256>>>(out);
}

// round 4
// speedup vs baseline: 4.4810x; 1.1994x over previous
#include <cuda_runtime.h>
#include <math.h>

#define BB 256
#define VV 50257
#define UU 65536
#define MM 3
#define NE (MM * VV)   // 150771 total (model, vocab) entries

// ---------------- scratch (device globals; no allocation at launch time) ----
__device__ float g_probsT[(size_t)MM * VV * BB];   // [m][j][b], b contiguous (1KB rows)
__device__ float g_rmax[MM * BB];
__device__ float g_scale[MM * BB];                 // w_m / sum_exp
__device__ int   g_count[UU];
__device__ int   g_off[UU + 1];
__device__ int   g_cursor[UU];
__device__ int   g_entries[NE];                    // packed pidx = m*VV + j

// ---------------- CSR inverse-map build ------------------------------------
__global__ void zero_counts() {
    int i = blockIdx.x * blockDim.x + threadIdx.x;
    if (i < UU) g_count[i] = 0;
}

__global__ void count_entries(const int* __restrict__ m0,
                              const int* __restrict__ m1,
                              const int* __restrict__ m2) {
    int idx = blockIdx.x * blockDim.x + threadIdx.x;
    if (idx >= NE) return;
    int m = idx / VV;
    int j = idx - m * VV;
    const int* mp = (m == 0) ? m0 : (m == 1) ? m1 : m2;
    atomicAdd(&g_count[mp[j]], 1);
}

// coalesced exclusive scan of 65536 counts: 1 block, 32 warps, warp-chunked
__global__ void scan_counts() {
    __shared__ int warp_tot[32];
    __shared__ int warp_pre[32];
    int t = threadIdx.x, lane = t & 31, w = t >> 5;
    const int CH = UU / 32;            // 2048 elements per warp
    int base = w * CH;

    int tot = 0;
    for (int i = lane; i < CH; i += 32) tot += g_count[base + i];
#pragma unroll
    for (int o = 16; o; o >>= 1) tot += __shfl_xor_sync(0xffffffffu, tot, o);
    if (lane == 0) warp_tot[w] = tot;
    __syncthreads();

    if (w == 0) {
        int v = warp_tot[lane];
        int s = v;
#pragma unroll
        for (int o = 1; o < 32; o <<= 1) {
            int x = __shfl_up_sync(0xffffffffu, s, o);
            if (lane >= o) s += x;
        }
        warp_pre[lane] = s - v;
        if (lane == 31) g_off[UU] = s;
    }
    __syncthreads();

    int run = warp_pre[w];
    for (int i = lane; i < CH; i += 32) {
        int v = g_count[base + i];
        int s = v;
#pragma unroll
        for (int o = 1; o < 32; o <<= 1) {
            int x = __shfl_up_sync(0xffffffffu, s, o);
            if (lane >= o) s += x;
        }
        int excl = run + s - v;
        g_off[base + i]    = excl;
        g_cursor[base + i] = excl;
        run += __shfl_sync(0xffffffffu, s, 31);
    }
}

__global__ void fill_entries(const int* __restrict__ m0,
                             const int* __restrict__ m1,
                             const int* __restrict__ m2) {
    int idx = blockIdx.x * blockDim.x + threadIdx.x;
    if (idx >= NE) return;
    int m = idx / VV;
    int j = idx - m * VV;
    const int* mp = (m == 0) ? m0 : (m == 1) ? m1 : m2;
    int u = mp[j];
    int pos = atomicAdd(&g_cursor[u], 1);
    g_entries[pos] = idx;   // pidx = m*VV + j
}

// canonicalize entry order within each bucket (determinism across replays)
__global__ void sort_buckets() {
    int u = blockIdx.x * blockDim.x + threadIdx.x;
    if (u >= UU) return;
    int s = g_off[u], e = g_off[u + 1];
    for (int i = s + 1; i < e; i++) {
        int key = g_entries[i];
        int k = i - 1;
        while (k >= s && g_entries[k] > key) { g_entries[k + 1] = g_entries[k]; k--; }
        g_entries[k + 1] = key;
    }
}

// ---------------- softmax row stats (online max/sum) ------------------------
__global__ void rowstats(const float* __restrict__ l0,
                         const float* __restrict__ l1,
                         const float* __restrict__ l2,
                         const float* __restrict__ w) {
    int b = blockIdx.x, m = blockIdx.y, t = threadIdx.x;
    const float* row = ((m == 0) ? l0 : (m == 1) ? l1 : l2) + (size_t)b * VV;
    float mx = -1e30f, sm = 0.f;
    for (int j = t; j < VV; j += 256) {
        float x = row[j];
        if (x > mx) { sm = sm * __expf(mx - x) + 1.f; mx = x; }
        else        { sm += __expf(x - mx); }
    }
    __shared__ float smx[256], ssm[256];
    smx[t] = mx; ssm[t] = sm;
    __syncthreads();
    for (int s = 128; s > 0; s >>= 1) {
        if (t < s) {
            float amx = smx[t], as = ssm[t], bmx = smx[t + s], bs = ssm[t + s];
            float Mx = fmaxf(amx, bmx);
            ssm[t] = as * __expf(amx - Mx) + bs * __expf(bmx - Mx);
            smx[t] = Mx;
        }
        __syncthreads();
    }
    if (t == 0) {
        g_rmax[m * BB + b]  = smx[0];
        g_scale[m * BB + b] = w[m] / ssm[0];
    }
}

// ---------------- exp + transpose: logits[b][j] -> probsT[m][j][b] ----------
__global__ void exp_transpose(const float* __restrict__ l0,
                              const float* __restrict__ l1,
                              const float* __restrict__ l2) {
    __shared__ float tile[32][33];
    int m  = blockIdx.z;
    int j0 = blockIdx.x * 32;
    int b0 = blockIdx.y * 32;
    const float* lg = (m == 0) ? l0 : (m == 1) ? l1 : l2;
    int tx = threadIdx.x, ty = threadIdx.y;   // (32, 8)

#pragma unroll
    for (int k = 0; k < 4; k++) {
        int bl = ty + k * 8;
        int j  = j0 + tx;
        int b  = b0 + bl;
        float v = 0.f;
        if (j < VV) {
            float x  = lg[(size_t)b * VV + j];
            int rid  = m * BB + b;
            v = __expf(x - g_rmax[rid]) * g_scale[rid];
        }
        tile[bl][tx] = v;
    }
    __syncthreads();
#pragma unroll
    for (int k = 0; k < 4; k++) {
        int jl = ty + k * 8;
        int j  = j0 + jl;
        if (j < VV)
            g_probsT[((size_t)m * VV + j) * BB + b0 + tx] = tile[tx][jl];
    }
}

// ---------------- gather v3: smem-staged entries, 4-bucket interleave (MLP=4)
#define GCAP 192
__global__ void gather_union(float* __restrict__ out) {
    __shared__ float tile[32][257];   // [ul][b], padded: conflict-free both phases
    __shared__ int soff[33];
    __shared__ int ent[GCAP];
    int u0 = blockIdx.x * 32;
    int t  = threadIdx.x;             // t == batch index in phase 1

    if (t < 33) soff[t] = g_off[u0 + t];
    __syncthreads();
    int s0 = soff[0];
    int n  = soff[32] - s0;           // total entries for this block (avg ~74)
    bool fits = (n <= GCAP);
    if (fits)
        for (int k = t; k < n; k += 256) ent[k] = g_entries[s0 + k];
    __syncthreads();

    for (int ug = 0; ug < 32; ug += 4) {
        int sA = soff[ug + 0] - s0, lA = soff[ug + 1] - soff[ug + 0];
        int sB = soff[ug + 1] - s0, lB = soff[ug + 2] - soff[ug + 1];
        int sC = soff[ug + 2] - s0, lC = soff[ug + 3] - soff[ug + 2];
        int sD = soff[ug + 3] - s0, lD = soff[ug + 4] - soff[ug + 3];
        float aA = 0.f, aB = 0.f, aC = 0.f, aD = 0.f;
        int L = max(max(lA, lB), max(lC, lD));
        if (fits) {
            for (int i = 0; i < L; i++) {
                // 4 independent load+acc streams -> MLP>=4; ent[] reads are
                // warp-uniform smem broadcasts
                if (i < lA) aA += g_probsT[(size_t)ent[sA + i] * BB + t];
                if (i < lB) aB += g_probsT[(size_t)ent[sB + i] * BB + t];
                if (i < lC) aC += g_probsT[(size_t)ent[sC + i] * BB + t];
                if (i < lD) aD += g_probsT[(size_t)ent[sD + i] * BB + t];
            }
        } else {
            for (int i = 0; i < L; i++) {
                if (i < lA) aA += g_probsT[(size_t)g_entries[s0 + sA + i] * BB + t];
                if (i < lB) aB += g_probsT[(size_t)g_entries[s0 + sB + i] * BB + t];
                if (i < lC) aC += g_probsT[(size_t)g_entries[s0 + sC + i] * BB + t];
                if (i < lD) aD += g_probsT[(size_t)g_entries[s0 + sD + i] * BB + t];
            }
        }
        tile[ug + 0][t] = aA;
        tile[ug + 1][t] = aB;
        tile[ug + 2][t] = aC;
        tile[ug + 3][t] = aD;
    }
    __syncthreads();
    // write out[b][u0..u0+31]: each 32-thread group -> one 128B transaction
    for (int it = 0; it < 32; it++) {
        int ul = t & 31;
        int b  = (t >> 5) + it * 8;
        out[(size_t)b * UU + u0 + ul] = tile[ul][b];
    }
}

// ---------------- launch -----------------------------------------------------
extern "C" void kernel_launch(void* const* d_in, const int* in_sizes, int n_in,
                              void* d_out, int out_size) {
    const float* l0 = (const float*)d_in[0];
    const float* l1 = (const float*)d_in[1];
    const float* l2 = (const float*)d_in[2];
    const int*   m0 = (const int*)d_in[3];
    const int*   m1 = (const int*)d_in[4];
    const int*   m2 = (const int*)d_in[5];
    const float* w  = (const float*)d_in[6];
    float* out = (float*)d_out;

    zero_counts<<<UU / 256, 256>>>();
    count_entries<<<(NE + 255) / 256, 256>>>(m0, m1, m2);
    scan_counts<<<1, 1024>>>();
    fill_entries<<<(NE + 255) / 256, 256>>>(m0, m1, m2);
    sort_buckets<<<UU / 256, 256>>>();

    rowstats<<<dim3(BB, MM), 256>>>(l0, l1, l2, w);
    exp_transpose<<<dim3((VV + 31) / 32, BB / 32, MM), dim3(32, 8)>>>(l0, l1, l2);
    gather_union<<<UU / 32, 256>>>(out);
}